// round 3
// baseline (speedup 1.0000x reference)
#include <cuda_runtime.h>
#include <math.h>

#define Bv 64
#define Tv 512
#define Iv 512
#define Hv 1024
#define Cv 128
#define G3 (3*Hv)
#define G2 (2*Hv)

// ---- static device scratch (no runtime allocation) ----
__device__ float g_xw_f[(size_t)Tv*Bv*G3];   // forward GRU input projections  [t*B+b, 3H]
__device__ float g_xw_b[(size_t)Tv*Bv*G3];   // backward GRU input projections
__device__ float g_xzr [(size_t)Tv*Bv*G2];   // TAGM zr input projections      [t*B+b, 2H]
__device__ float g_xt  [(size_t)Tv*Bv*Hv];   // TAGM t  input projections      [t*B+b, H]
__device__ float g_hf  [(size_t)Tv*Bv*Hv];   // forward GRU hidden states per t
__device__ float g_hb  [(size_t)Tv*Bv*Hv];   // backward GRU hidden states per t
__device__ float g_hh  [(size_t)Tv*Bv*Hv];   // TAGM hidden history (one slot per step)
__device__ float g_att [Tv*Bv];              // attention gate a[t,b]

// grid-barrier state: 3 groups (fwd GRU, bwd GRU, TAGM), padded to distinct lines
__device__ unsigned g_bar_cnt[3*32];
__device__ unsigned g_bar_gen[3*32];

__device__ __forceinline__ float sigmoidf_(float x) { return 1.0f / (1.0f + expf(-x)); }

// packed f32x2 FMA: d(lo,hi) += a(lo,hi) * b(lo,hi)
__device__ __forceinline__ void fma2(unsigned long long& d,
                                     unsigned long long a, unsigned long long b) {
    asm("fma.rn.f32x2 %0, %1, %2, %0;" : "+l"(d) : "l"(a), "l"(b));
}
__device__ __forceinline__ float hsum2(unsigned long long v) {
    float lo, hi;
    asm("mov.b64 {%0,%1}, %2;" : "=f"(lo), "=f"(hi) : "l"(v));
    return lo + hi;
}

// sense-reversing grid barrier among nb blocks (group grp)
__device__ __forceinline__ void grid_bar(int grp, unsigned nb) {
    volatile unsigned* gen = (volatile unsigned*)&g_bar_gen[grp*32];
    unsigned* cnt = &g_bar_cnt[grp*32];
    __threadfence();          // publish this block's stores (all threads)
    __syncthreads();
    if (threadIdx.x == 0) {
        unsigned g = *gen;
        if (atomicAdd(cnt, 1u) == nb - 1) {
            atomicExch(cnt, 0u);
            __threadfence();
            *gen = g + 1;
        } else {
            while (*gen == g) __nanosleep(64);
            __threadfence();
        }
    }
    __syncthreads();
}

// ============================================================================
// Input projection GEMM: out[r, n] = sum_i x_tb(r,i) * W[n,i] + bias[n]
//   r = t*B + b, x is [B,T,I] row-major, W is [N,I] row-major, K = I = 512.
//   BM=128, BN=64, BK=16; 256 threads; 8x4 microtile; k-packed f32x2 FMA.
// ============================================================================
__global__ void __launch_bounds__(256) proj_gemm(
    const float* __restrict__ x, const float* __restrict__ W,
    const float* __restrict__ bias, float* __restrict__ out, int N)
{
    __shared__ __align__(16) float sa[128][36];  // [m][k], 144B stride
    __shared__ __align__(16) float sw[64][36];   // [n][k]

    const int tid = threadIdx.x;
    const int tx = tid & 15;       // n-lane
    const int ty = tid >> 4;       // m-lane
    const int m0 = blockIdx.y * 128;
    const int n0 = blockIdx.x * 64;

    unsigned long long acc[8][4] = {};

    for (int k0 = 0; k0 < Iv; k0 += 16) {
        #pragma unroll
        for (int q = 0; q < 2; q++) {
            int idx = tid + 256 * q;
            int m = idx >> 2, kq = idx & 3;
            int r = m0 + m;
            int b = r & 63, t = r >> 6;
            float4 v = *(const float4*)(x + ((size_t)b * Tv + t) * Iv + k0 + kq * 4);
            *(float4*)&sa[m][kq * 4] = v;
        }
        {
            int n = tid >> 2, kq = tid & 3;
            float4 v = *(const float4*)(W + (size_t)(n0 + n) * Iv + k0 + kq * 4);
            *(float4*)&sw[n][kq * 4] = v;
        }
        __syncthreads();
        #pragma unroll
        for (int kq = 0; kq < 4; kq++) {
            ulonglong2 wv[4];
            #pragma unroll
            for (int nn = 0; nn < 4; nn++)
                wv[nn] = *(const ulonglong2*)&sw[tx + nn * 16][kq * 4];
            #pragma unroll
            for (int mm = 0; mm < 8; mm++) {
                ulonglong2 av = *(const ulonglong2*)&sa[ty + mm * 16][kq * 4];
                #pragma unroll
                for (int nn = 0; nn < 4; nn++) {
                    fma2(acc[mm][nn], av.x, wv[nn].x);
                    fma2(acc[mm][nn], av.y, wv[nn].y);
                }
            }
        }
        __syncthreads();
    }

    #pragma unroll
    for (int mm = 0; mm < 8; mm++) {
        int r = m0 + ty + mm * 16;
        #pragma unroll
        for (int nn = 0; nn < 4; nn++) {
            int n = n0 + tx + nn * 16;
            out[(size_t)r * N + n] = hsum2(acc[mm][nn]) + bias[n];
        }
    }
}

// ============================================================================
// Persistent bidirectional GRU: 256 blocks (0..127 fwd, 128..255 bwd), 128 thr.
//   Per step each block computes 8 hidden cols x 3 gates x 64 batch.
//   Per-direction grid barrier between steps.
// ============================================================================
__global__ void __launch_bounds__(128, 2) gru_persist(
    const float* __restrict__ wh_f, const float* __restrict__ wh_b,
    const float* __restrict__ bh_f, const float* __restrict__ bh_b)
{
    __shared__ __align__(16) float sh[64][68];   // h_prev chunk [b][k]
    __shared__ __align__(16) float sw[24][68];   // weight rows [g*8+jj][k]

    const int tid  = threadIdx.x;
    const int dir  = blockIdx.x >> 7;
    const int jblk = blockIdx.x & 127;
    const int j0   = jblk * 8;
    const int jl   = tid & 7;
    const int bg   = tid >> 3;     // 0..15

    const float* wh = dir ? wh_b : wh_f;
    const float* bh = dir ? bh_b : bh_f;
    const float* xwbase = dir ? g_xw_b : g_xw_f;
    float* hbuf = dir ? g_hb : g_hf;

    const int j = j0 + jl;
    const float bhr = bh[j], bhz = bh[Hv + j], bhn = bh[2*Hv + j];

    for (int s = 0; s < Tv; s++) {
        const int t = dir ? (Tv - 1 - s) : s;
        const int tprev = dir ? t + 1 : t - 1;
        const float* xw = xwbase + (size_t)t * Bv * G3;
        float* hcur = hbuf + (size_t)t * Bv * Hv;
        const float* hprev = hbuf + (size_t)(s ? tprev : t) * Bv * Hv;

        unsigned long long acc2[3][4] = {};

        if (s) {
            for (int k0 = 0; k0 < Hv; k0 += 64) {
                #pragma unroll
                for (int u = 0; u < 8; u++) {
                    int idx = tid + 128 * u;
                    int bb = idx >> 4, kq = idx & 15;
                    float4 v = *(const float4*)(hprev + (size_t)bb * Hv + k0 + kq * 4);
                    *(float4*)&sh[bb][kq * 4] = v;
                }
                #pragma unroll
                for (int u = 0; u < 3; u++) {
                    int idx = tid + 128 * u;
                    int row = idx >> 4, kq = idx & 15;
                    int g = row >> 3, jj = row & 7;
                    float4 v = *(const float4*)(wh + (size_t)(g * Hv + j0 + jj) * Hv + k0 + kq * 4);
                    *(float4*)&sw[row][kq * 4] = v;
                }
                __syncthreads();
                #pragma unroll
                for (int kk = 0; kk < 16; kk++) {
                    ulonglong2 w0 = *(const ulonglong2*)&sw[jl      ][kk * 4];
                    ulonglong2 w1 = *(const ulonglong2*)&sw[8  + jl ][kk * 4];
                    ulonglong2 w2 = *(const ulonglong2*)&sw[16 + jl ][kk * 4];
                    #pragma unroll
                    for (int bb = 0; bb < 4; bb++) {
                        ulonglong2 hv = *(const ulonglong2*)&sh[bg * 4 + bb][kk * 4];
                        fma2(acc2[0][bb], hv.x, w0.x); fma2(acc2[0][bb], hv.y, w0.y);
                        fma2(acc2[1][bb], hv.x, w1.x); fma2(acc2[1][bb], hv.y, w1.y);
                        fma2(acc2[2][bb], hv.x, w2.x); fma2(acc2[2][bb], hv.y, w2.y);
                    }
                }
                __syncthreads();
            }
        }

        #pragma unroll
        for (int bb = 0; bb < 4; bb++) {
            int b = bg * 4 + bb;
            const float* xwb = xw + (size_t)b * G3;
            float r = sigmoidf_(xwb[j]          + hsum2(acc2[0][bb]) + bhr);
            float z = sigmoidf_(xwb[Hv + j]     + hsum2(acc2[1][bb]) + bhz);
            float n = tanhf    (xwb[2*Hv + j]   + r * (hsum2(acc2[2][bb]) + bhn));
            float hp = s ? hprev[(size_t)b * Hv + j] : 0.0f;
            hcur[(size_t)b * Hv + j] = (1.0f - z) * n + z * hp;
        }

        if (s != Tv - 1) grid_bar(dir, 128);
    }
}

// ============================================================================
// Attention logits: att[t,b] = sigmoid(3 * (hf.w[0:H] + hb.w[H:2H] + b))
// Also writes transposed attention output [B,T] into d_out.
// ============================================================================
__global__ void att_kernel(const float* __restrict__ fcw, const float* __restrict__ fcb,
                           float* __restrict__ out_att)
{
    const int t = blockIdx.x;
    const int w = threadIdx.x >> 5, lane = threadIdx.x & 31;
    for (int rep = 0; rep < 8; rep++) {
        int b = w + rep * 8;
        const float* hf = g_hf + (size_t)(t * Bv + b) * Hv;
        const float* hb = g_hb + (size_t)(t * Bv + b) * Hv;
        float acc = 0.0f;
        for (int k = lane; k < Hv; k += 32)
            acc += hf[k] * fcw[k] + hb[k] * fcw[Hv + k];
        #pragma unroll
        for (int o = 16; o; o >>= 1) acc += __shfl_xor_sync(0xffffffffu, acc, o);
        if (lane == 0) {
            float a = sigmoidf_(3.0f * (acc + fcb[0]));
            g_att[t * Bv + b] = a;
            out_att[(size_t)b * Tv + t] = a;
        }
    }
}

// ============================================================================
// Persistent TAGM recurrence: 128 blocks, hidden history in g_hh (no reuse ->
// no cross-SM L1 staleness). Grid barrier among all 128 blocks per step.
// ============================================================================
__global__ void __launch_bounds__(128, 2) tagm_persist(
    const float* __restrict__ wzr, const float* __restrict__ bzr,
    const float* __restrict__ wt,  const float* __restrict__ bt)
{
    __shared__ __align__(16) float sh[64][68];
    __shared__ __align__(16) float sw[24][68];

    const int tid = threadIdx.x;
    const int j0  = blockIdx.x * 8;
    const int jl  = tid & 7;
    const int bg  = tid >> 3;

    const int j = j0 + jl;
    const float br = bzr[j], bz = bzr[Hv + j], btt = bt[j];

    for (int s = 0; s < Tv; s++) {
        const float* hprev = g_hh + (size_t)(s ? s - 1 : 0) * Bv * Hv;
        float*       hnext = g_hh + (size_t)s * Bv * Hv;

        unsigned long long acc2[3][4] = {};

        if (s) {
            for (int k0 = 0; k0 < Hv; k0 += 64) {
                #pragma unroll
                for (int u = 0; u < 8; u++) {
                    int idx = tid + 128 * u;
                    int bb = idx >> 4, kq = idx & 15;
                    float4 v = *(const float4*)(hprev + (size_t)bb * Hv + k0 + kq * 4);
                    *(float4*)&sh[bb][kq * 4] = v;
                }
                #pragma unroll
                for (int u = 0; u < 3; u++) {
                    int idx = tid + 128 * u;
                    int row = idx >> 4, kq = idx & 15;
                    int g = row >> 3, jj = row & 7;
                    const float* src = (g == 2) ? (wt + (size_t)(j0 + jj) * Hv)
                                                : (wzr + (size_t)(g * Hv + j0 + jj) * Hv);
                    float4 v = *(const float4*)(src + k0 + kq * 4);
                    *(float4*)&sw[row][kq * 4] = v;
                }
                __syncthreads();
                #pragma unroll
                for (int kk = 0; kk < 16; kk++) {
                    ulonglong2 w0 = *(const ulonglong2*)&sw[jl      ][kk * 4];
                    ulonglong2 w1 = *(const ulonglong2*)&sw[8  + jl ][kk * 4];
                    ulonglong2 w2 = *(const ulonglong2*)&sw[16 + jl ][kk * 4];
                    #pragma unroll
                    for (int bb = 0; bb < 4; bb++) {
                        ulonglong2 hv = *(const ulonglong2*)&sh[bg * 4 + bb][kk * 4];
                        fma2(acc2[0][bb], hv.x, w0.x); fma2(acc2[0][bb], hv.y, w0.y);
                        fma2(acc2[1][bb], hv.x, w1.x); fma2(acc2[1][bb], hv.y, w1.y);
                        fma2(acc2[2][bb], hv.x, w2.x); fma2(acc2[2][bb], hv.y, w2.y);
                    }
                }
                __syncthreads();
            }
        }

        #pragma unroll
        for (int bb = 0; bb < 4; bb++) {
            int b = bg * 4 + bb;
            const float* xzrb = g_xzr + (size_t)(s * Bv + b) * G2;
            float a  = g_att[s * Bv + b];
            float r  = sigmoidf_(xzrb[j]      + hsum2(acc2[0][bb]) + br);
            float z  = sigmoidf_(xzrb[Hv + j] + hsum2(acc2[1][bb]) + bz);
            float ht = tanhf(g_xt[(size_t)(s * Bv + b) * Hv + j] + r * (hsum2(acc2[2][bb]) + btt));
            float hp = s ? hprev[(size_t)b * Hv + j] : 0.0f;
            hnext[(size_t)b * Hv + j] = a * (z * ht + (1.0f - z) * hp);
        }

        if (s != Tv - 1) grid_bar(2, 128);
    }
}

// ============================================================================
// fc0: out[b,c] = h_last[b,:] . fc0_w[c,:] + fc0_b[c]   (h_last = g_hh[T-1])
// ============================================================================
__global__ void fc0_kernel(const float* __restrict__ w, const float* __restrict__ bias,
                           float* __restrict__ out)
{
    const int b = blockIdx.x;
    const int wp = threadIdx.x >> 5, lane = threadIdx.x & 31;
    const float* h = g_hh + (size_t)(Tv - 1) * Bv * Hv + (size_t)b * Hv;
    for (int c = wp; c < Cv; c += 8) {
        float acc = 0.0f;
        for (int k = lane; k < Hv; k += 32) acc += h[k] * w[(size_t)c * Hv + k];
        #pragma unroll
        for (int o = 16; o; o >>= 1) acc += __shfl_xor_sync(0xffffffffu, acc, o);
        if (lane == 0) out[(size_t)b * Cv + c] = acc + bias[c];
    }
}

// ============================================================================
extern "C" void kernel_launch(void* const* d_in, const int* in_sizes, int n_in,
                              void* d_out, int out_size)
{
    const float* x        = (const float*)d_in[0];
    const float* att_wi_f = (const float*)d_in[1];
    const float* att_wh_f = (const float*)d_in[2];
    const float* att_bi_f = (const float*)d_in[3];
    const float* att_bh_f = (const float*)d_in[4];
    const float* att_wi_b = (const float*)d_in[5];
    const float* att_wh_b = (const float*)d_in[6];
    const float* att_bi_b = (const float*)d_in[7];
    const float* att_bh_b = (const float*)d_in[8];
    const float* att_fc_w = (const float*)d_in[9];
    const float* att_fc_b = (const float*)d_in[10];
    const float* w_i2h_zr = (const float*)d_in[11];
    const float* b_i2h_zr = (const float*)d_in[12];
    const float* w_h2h_zr = (const float*)d_in[13];
    const float* b_h2h_zr = (const float*)d_in[14];
    const float* w_i2h_t  = (const float*)d_in[15];
    const float* b_i2h_t  = (const float*)d_in[16];
    const float* w_h2h_t  = (const float*)d_in[17];
    const float* b_h2h_t  = (const float*)d_in[18];
    const float* fc0_w    = (const float*)d_in[19];
    const float* fc0_b    = (const float*)d_in[20];

    float* out     = (float*)d_out;
    float* out_att = out + Bv * Cv;

    float *p_xwf, *p_xwb, *p_xzr, *p_xt;
    cudaGetSymbolAddress((void**)&p_xwf, g_xw_f);
    cudaGetSymbolAddress((void**)&p_xwb, g_xw_b);
    cudaGetSymbolAddress((void**)&p_xzr, g_xzr);
    cudaGetSymbolAddress((void**)&p_xt,  g_xt);

    // 1) input projections (parallel GEMMs)
    proj_gemm<<<dim3(G3 / 64, (Tv * Bv) / 128), 256>>>(x, att_wi_f, att_bi_f, p_xwf, G3);
    proj_gemm<<<dim3(G3 / 64, (Tv * Bv) / 128), 256>>>(x, att_wi_b, att_bi_b, p_xwb, G3);
    proj_gemm<<<dim3(G2 / 64, (Tv * Bv) / 128), 256>>>(x, w_i2h_zr, b_i2h_zr, p_xzr, G2);
    proj_gemm<<<dim3(Hv / 64, (Tv * Bv) / 128), 256>>>(x, w_i2h_t,  b_i2h_t,  p_xt,  Hv);

    // 2) bidirectional GRU recurrence — single persistent launch
    gru_persist<<<256, 128>>>(att_wh_f, att_wh_b, att_bh_f, att_bh_b);

    // 3) attention gate
    att_kernel<<<Tv, 256>>>(att_fc_w, att_fc_b, out_att);

    // 4) TAGM recurrence — single persistent launch
    tagm_persist<<<128, 128>>>(w_h2h_zr, b_h2h_zr, w_h2h_t, b_h2h_t);

    // 5) final projection
    fc0_kernel<<<Bv, 256>>>(fc0_w, fc0_b, out);
}

// round 4
// speedup vs baseline: 1.1457x; 1.1457x over previous
#include <cuda_runtime.h>
#include <math.h>

#define Bv 64
#define Tv 512
#define Iv 512
#define Hv 1024
#define Cv 128
#define G3 (3*Hv)
#define G2 (2*Hv)

// ---- static device scratch (no runtime allocation) ----
__device__ float g_xw_f[(size_t)Tv*Bv*G3];   // forward GRU input projections  [t*B+b, 3H]
__device__ float g_xw_b[(size_t)Tv*Bv*G3];   // backward GRU input projections
__device__ float g_xzr [(size_t)Tv*Bv*G2];   // TAGM zr input projections      [t*B+b, 2H]
__device__ float g_xt  [(size_t)Tv*Bv*Hv];   // TAGM t  input projections      [t*B+b, H]
__device__ float g_hf  [(size_t)Tv*Bv*Hv];   // forward GRU hidden states per t
__device__ float g_hb  [(size_t)Tv*Bv*Hv];   // backward GRU hidden states per t
__device__ float g_hh  [(size_t)Tv*Bv*Hv];   // TAGM hidden history (one slot per step)
__device__ float g_att [Tv*Bv];              // attention gate a[t,b]
// split-K partial buffers (address-reused every step -> readers use __ldcg)
__device__ float g_pgru[(size_t)4*2*Bv*G3];  // [kb][dir][b][3072]
__device__ float g_ptag[(size_t)8*Bv*G3];    // [kb][b][3072]

// grid-barrier state: 3 groups (fwd GRU, bwd GRU, TAGM), padded lines
__device__ unsigned g_bar_cnt[3*32];
__device__ unsigned g_bar_gen[3*32];

__device__ __forceinline__ float sigmoidf_(float x) { return 1.0f / (1.0f + expf(-x)); }

// packed f32x2 FMA: d(lo,hi) += a(lo,hi) * b(lo,hi)
__device__ __forceinline__ void fma2(unsigned long long& d,
                                     unsigned long long a, unsigned long long b) {
    asm("fma.rn.f32x2 %0, %1, %2, %0;" : "+l"(d) : "l"(a), "l"(b));
}
__device__ __forceinline__ float hsum2(unsigned long long v) {
    float lo, hi;
    asm("mov.b64 {%0,%1}, %2;" : "=f"(lo), "=f"(hi) : "l"(v));
    return lo + hi;
}

// sense-reversing grid barrier among nb blocks (group grp)
__device__ __forceinline__ void grid_bar(int grp, unsigned nb) {
    volatile unsigned* gen = (volatile unsigned*)&g_bar_gen[grp*32];
    unsigned* cnt = &g_bar_cnt[grp*32];
    __threadfence();
    __syncthreads();
    if (threadIdx.x == 0) {
        unsigned g = *gen;
        if (atomicAdd(cnt, 1u) == nb - 1) {
            atomicExch(cnt, 0u);
            __threadfence();
            *gen = g + 1;
        } else {
            while (*gen == g) __nanosleep(64);
            __threadfence();
        }
    }
    __syncthreads();
}

// ============================================================================
// Input projection GEMM: out[r, n] = sum_i x_tb(r,i) * W[n,i] + bias[n]
// ============================================================================
__global__ void __launch_bounds__(256, 2) proj_gemm(
    const float* __restrict__ x, const float* __restrict__ W,
    const float* __restrict__ bias, float* __restrict__ out, int N)
{
    __shared__ __align__(16) float sa[128][36];
    __shared__ __align__(16) float sw[64][36];

    const int tid = threadIdx.x;
    const int tx = tid & 15;
    const int ty = tid >> 4;
    const int m0 = blockIdx.y * 128;
    const int n0 = blockIdx.x * 64;

    unsigned long long acc[8][4] = {};

    for (int k0 = 0; k0 < Iv; k0 += 16) {
        #pragma unroll
        for (int q = 0; q < 2; q++) {
            int idx = tid + 256 * q;
            int m = idx >> 2, kq = idx & 3;
            int r = m0 + m;
            int b = r & 63, t = r >> 6;
            float4 v = *(const float4*)(x + ((size_t)b * Tv + t) * Iv + k0 + kq * 4);
            *(float4*)&sa[m][kq * 4] = v;
        }
        {
            int n = tid >> 2, kq = tid & 3;
            float4 v = *(const float4*)(W + (size_t)(n0 + n) * Iv + k0 + kq * 4);
            *(float4*)&sw[n][kq * 4] = v;
        }
        __syncthreads();
        #pragma unroll
        for (int kq = 0; kq < 4; kq++) {
            ulonglong2 wv[4];
            #pragma unroll
            for (int nn = 0; nn < 4; nn++)
                wv[nn] = *(const ulonglong2*)&sw[tx + nn * 16][kq * 4];
            #pragma unroll
            for (int mm = 0; mm < 8; mm++) {
                ulonglong2 av = *(const ulonglong2*)&sa[ty + mm * 16][kq * 4];
                #pragma unroll
                for (int nn = 0; nn < 4; nn++) {
                    fma2(acc[mm][nn], av.x, wv[nn].x);
                    fma2(acc[mm][nn], av.y, wv[nn].y);
                }
            }
        }
        __syncthreads();
    }

    #pragma unroll
    for (int mm = 0; mm < 8; mm++) {
        int r = m0 + ty + mm * 16;
        #pragma unroll
        for (int nn = 0; nn < 4; nn++) {
            int n = n0 + tx + nn * 16;
            out[(size_t)r * N + n] = hsum2(acc[mm][nn]) + bias[n];
        }
    }
}

// ============================================================================
// Persistent bidirectional GRU with split-K.
//   256 blocks x 128 thr (2/SM). dir = blk>>7. Within dir (bid 0..127):
//   Phase A: gate-tile gt=bid>>2 (96 gates), k-split kb=bid&3 (k=256),
//            8b x 6g microtile per thread (FFMA2, k-packed) -> partials.
//   Phase B: j0=bid*8 -> reduce partials, gate nonlinearity, write h(t).
// ============================================================================
__global__ void __launch_bounds__(128, 2) gru_persist(
    const float* __restrict__ wh_f, const float* __restrict__ wh_b,
    const float* __restrict__ bh_f, const float* __restrict__ bh_b)
{
    __shared__ __align__(16) float sh[64][68];
    __shared__ __align__(16) float sw[96][68];

    const int tid = threadIdx.x;
    const int dir = blockIdx.x >> 7;
    const int bid = blockIdx.x & 127;
    const int gt  = bid >> 2;      // 0..31
    const int kb  = bid & 3;       // 0..3
    const int gx  = tid & 15;      // g-lane
    const int by  = tid >> 4;      // 0..7 (b-group of 8)
    const int jl  = tid & 7;
    const int bq  = tid >> 3;      // 0..15

    const float* wh = dir ? wh_b : wh_f;
    const float* bh = dir ? bh_b : bh_f;
    const float* xwbase = dir ? g_xw_b : g_xw_f;
    float* hbuf = dir ? g_hb : g_hf;
    float* mypart = g_pgru + ((size_t)(kb * 2 + dir)) * Bv * G3;

    const int j = bid * 8 + jl;
    const float bhr = bh[j], bhz = bh[Hv + j], bhn = bh[2*Hv + j];
    const float* wrow = wh + (size_t)(gt * 96) * Hv;

    for (int s = 0; s < Tv; s++) {
        const int t = dir ? (Tv - 1 - s) : s;
        const int tprev = dir ? t + 1 : t - 1;

        // ---------------- phase A: partial GEMM ----------------
        if (s) {
            const float* hp = hbuf + (size_t)tprev * Bv * Hv;
            unsigned long long acc[8][6] = {};
            #pragma unroll 1
            for (int c = 0; c < 4; c++) {
                const int k0 = kb * 256 + c * 64;
                #pragma unroll
                for (int u = 0; u < 8; u++) {
                    int idx = tid + 128 * u;
                    int bb = idx >> 4, kq = idx & 15;
                    *(float4*)&sh[bb][kq * 4] =
                        *(const float4*)(hp + (size_t)bb * Hv + k0 + kq * 4);
                }
                #pragma unroll
                for (int u = 0; u < 12; u++) {
                    int idx = tid + 128 * u;
                    int r = idx >> 4, kq = idx & 15;
                    *(float4*)&sw[r][kq * 4] =
                        *(const float4*)(wrow + (size_t)r * Hv + k0 + kq * 4);
                }
                __syncthreads();
                #pragma unroll
                for (int kk = 0; kk < 16; kk++) {
                    ulonglong2 wv[6];
                    #pragma unroll
                    for (int v = 0; v < 6; v++)
                        wv[v] = *(const ulonglong2*)&sw[gx + 16 * v][kk * 4];
                    #pragma unroll
                    for (int u = 0; u < 8; u++) {
                        ulonglong2 hv = *(const ulonglong2*)&sh[by * 8 + u][kk * 4];
                        #pragma unroll
                        for (int v = 0; v < 6; v++) {
                            fma2(acc[u][v], hv.x, wv[v].x);
                            fma2(acc[u][v], hv.y, wv[v].y);
                        }
                    }
                }
                __syncthreads();
            }
            #pragma unroll
            for (int u = 0; u < 8; u++) {
                float* prow = mypart + (size_t)(by * 8 + u) * G3 + gt * 96 + gx;
                #pragma unroll
                for (int v = 0; v < 6; v++)
                    prow[16 * v] = hsum2(acc[u][v]);
            }
        }

        grid_bar(dir, 128);

        // ---------------- phase B: reduce + gates ----------------
        {
            const float* xw = xwbase + (size_t)t * Bv * G3;
            float* hcur = hbuf + (size_t)t * Bv * Hv;
            const float* hp = hbuf + (size_t)(s ? tprev : t) * Bv * Hv;
            #pragma unroll
            for (int u = 0; u < 4; u++) {
                int b = bq * 4 + u;
                float ra = 0.f, za = 0.f, na = 0.f;
                if (s) {
                    #pragma unroll
                    for (int k2 = 0; k2 < 4; k2++) {
                        const float* p = g_pgru + ((size_t)(k2 * 2 + dir)) * Bv * G3
                                       + (size_t)b * G3;
                        ra += __ldcg(p + j);
                        za += __ldcg(p + Hv + j);
                        na += __ldcg(p + 2 * Hv + j);
                    }
                }
                const float* xwb = xw + (size_t)b * G3;
                float r = sigmoidf_(xwb[j]          + ra + bhr);
                float z = sigmoidf_(xwb[Hv + j]     + za + bhz);
                float n = tanhf    (xwb[2*Hv + j]   + r * (na + bhn));
                float hpv = s ? hp[(size_t)b * Hv + j] : 0.0f;
                hcur[(size_t)b * Hv + j] = (1.0f - z) * n + z * hpv;
            }
        }

        if (s != Tv - 1) grid_bar(dir, 128);
    }
}

// ============================================================================
// Attention logits
// ============================================================================
__global__ void att_kernel(const float* __restrict__ fcw, const float* __restrict__ fcb,
                           float* __restrict__ out_att)
{
    const int t = blockIdx.x;
    const int w = threadIdx.x >> 5, lane = threadIdx.x & 31;
    for (int rep = 0; rep < 8; rep++) {
        int b = w + rep * 8;
        const float* hf = g_hf + (size_t)(t * Bv + b) * Hv;
        const float* hb = g_hb + (size_t)(t * Bv + b) * Hv;
        float acc = 0.0f;
        for (int k = lane; k < Hv; k += 32)
            acc += hf[k] * fcw[k] + hb[k] * fcw[Hv + k];
        #pragma unroll
        for (int o = 16; o; o >>= 1) acc += __shfl_xor_sync(0xffffffffu, acc, o);
        if (lane == 0) {
            float a = sigmoidf_(3.0f * (acc + fcb[0]));
            g_att[t * Bv + b] = a;
            out_att[(size_t)b * Tv + t] = a;
        }
    }
}

// ============================================================================
// Persistent TAGM with split-K: 256 blocks x 128 thr.
//   Phase A: gt=bid>>3 (96 gates), kb=bid&7 (k=128). Virtual weight rows:
//   g<2048 -> wzr[g], else wt[g-2048].
//   Phase B: j0=bid*4, 2 outputs/thread, reduce 8 k-splits.
// ============================================================================
__global__ void __launch_bounds__(128, 2) tagm_persist(
    const float* __restrict__ wzr, const float* __restrict__ bzr,
    const float* __restrict__ wt,  const float* __restrict__ bt)
{
    __shared__ __align__(16) float sh[64][68];
    __shared__ __align__(16) float sw[96][68];

    const int tid = threadIdx.x;
    const int bid = blockIdx.x;    // 0..255
    const int gt  = bid >> 3;      // 0..31
    const int kb  = bid & 7;       // 0..7
    const int gx  = tid & 15;
    const int by  = tid >> 4;
    const int jl  = tid & 3;
    const int bqq = tid >> 2;      // 0..31

    float* mypart = g_ptag + (size_t)kb * Bv * G3;
    const int j = bid * 4 + jl;
    const float br = bzr[j], bz = bzr[Hv + j], btt = bt[j];

    for (int s = 0; s < Tv; s++) {
        // ---------------- phase A ----------------
        if (s) {
            const float* hp = g_hh + (size_t)(s - 1) * Bv * Hv;
            unsigned long long acc[8][6] = {};
            #pragma unroll 1
            for (int c = 0; c < 2; c++) {
                const int k0 = kb * 128 + c * 64;
                #pragma unroll
                for (int u = 0; u < 8; u++) {
                    int idx = tid + 128 * u;
                    int bb = idx >> 4, kq = idx & 15;
                    *(float4*)&sh[bb][kq * 4] =
                        *(const float4*)(hp + (size_t)bb * Hv + k0 + kq * 4);
                }
                #pragma unroll
                for (int u = 0; u < 12; u++) {
                    int idx = tid + 128 * u;
                    int r = idx >> 4, kq = idx & 15;
                    int gr = gt * 96 + r;
                    const float* src = (gr < G2) ? (wzr + (size_t)gr * Hv)
                                                 : (wt + (size_t)(gr - G2) * Hv);
                    *(float4*)&sw[r][kq * 4] = *(const float4*)(src + k0 + kq * 4);
                }
                __syncthreads();
                #pragma unroll
                for (int kk = 0; kk < 16; kk++) {
                    ulonglong2 wv[6];
                    #pragma unroll
                    for (int v = 0; v < 6; v++)
                        wv[v] = *(const ulonglong2*)&sw[gx + 16 * v][kk * 4];
                    #pragma unroll
                    for (int u = 0; u < 8; u++) {
                        ulonglong2 hv = *(const ulonglong2*)&sh[by * 8 + u][kk * 4];
                        #pragma unroll
                        for (int v = 0; v < 6; v++) {
                            fma2(acc[u][v], hv.x, wv[v].x);
                            fma2(acc[u][v], hv.y, wv[v].y);
                        }
                    }
                }
                __syncthreads();
            }
            #pragma unroll
            for (int u = 0; u < 8; u++) {
                float* prow = mypart + (size_t)(by * 8 + u) * G3 + gt * 96 + gx;
                #pragma unroll
                for (int v = 0; v < 6; v++)
                    prow[16 * v] = hsum2(acc[u][v]);
            }
        }

        grid_bar(2, 256);

        // ---------------- phase B ----------------
        {
            const float* hp = g_hh + (size_t)(s ? s - 1 : 0) * Bv * Hv;
            float* hnext = g_hh + (size_t)s * Bv * Hv;
            #pragma unroll
            for (int u = 0; u < 2; u++) {
                int b = bqq + 32 * u;
                float ra = 0.f, za = 0.f, na = 0.f;
                if (s) {
                    #pragma unroll
                    for (int k2 = 0; k2 < 8; k2++) {
                        const float* p = g_ptag + (size_t)k2 * Bv * G3 + (size_t)b * G3;
                        ra += __ldcg(p + j);
                        za += __ldcg(p + Hv + j);
                        na += __ldcg(p + 2 * Hv + j);
                    }
                }
                const float* xzrb = g_xzr + (size_t)(s * Bv + b) * G2;
                float a  = g_att[s * Bv + b];
                float r  = sigmoidf_(xzrb[j]      + ra + br);
                float z  = sigmoidf_(xzrb[Hv + j] + za + bz);
                float ht = tanhf(g_xt[(size_t)(s * Bv + b) * Hv + j] + r * (na + btt));
                float hpv = s ? hp[(size_t)b * Hv + j] : 0.0f;
                hnext[(size_t)b * Hv + j] = a * (z * ht + (1.0f - z) * hpv);
            }
        }

        if (s != Tv - 1) grid_bar(2, 256);
    }
}

// ============================================================================
// fc0: out[b,c] = h_last[b,:] . fc0_w[c,:] + fc0_b[c]
// ============================================================================
__global__ void fc0_kernel(const float* __restrict__ w, const float* __restrict__ bias,
                           float* __restrict__ out)
{
    const int b = blockIdx.x;
    const int wp = threadIdx.x >> 5, lane = threadIdx.x & 31;
    const float* h = g_hh + (size_t)(Tv - 1) * Bv * Hv + (size_t)b * Hv;
    for (int c = wp; c < Cv; c += 8) {
        float acc = 0.0f;
        for (int k = lane; k < Hv; k += 32) acc += h[k] * w[(size_t)c * Hv + k];
        #pragma unroll
        for (int o = 16; o; o >>= 1) acc += __shfl_xor_sync(0xffffffffu, acc, o);
        if (lane == 0) out[(size_t)b * Cv + c] = acc + bias[c];
    }
}

// ============================================================================
extern "C" void kernel_launch(void* const* d_in, const int* in_sizes, int n_in,
                              void* d_out, int out_size)
{
    const float* x        = (const float*)d_in[0];
    const float* att_wi_f = (const float*)d_in[1];
    const float* att_wh_f = (const float*)d_in[2];
    const float* att_bi_f = (const float*)d_in[3];
    const float* att_bh_f = (const float*)d_in[4];
    const float* att_wi_b = (const float*)d_in[5];
    const float* att_wh_b = (const float*)d_in[6];
    const float* att_bi_b = (const float*)d_in[7];
    const float* att_bh_b = (const float*)d_in[8];
    const float* att_fc_w = (const float*)d_in[9];
    const float* att_fc_b = (const float*)d_in[10];
    const float* w_i2h_zr = (const float*)d_in[11];
    const float* b_i2h_zr = (const float*)d_in[12];
    const float* w_h2h_zr = (const float*)d_in[13];
    const float* b_h2h_zr = (const float*)d_in[14];
    const float* w_i2h_t  = (const float*)d_in[15];
    const float* b_i2h_t  = (const float*)d_in[16];
    const float* w_h2h_t  = (const float*)d_in[17];
    const float* b_h2h_t  = (const float*)d_in[18];
    const float* fc0_w    = (const float*)d_in[19];
    const float* fc0_b    = (const float*)d_in[20];

    float* out     = (float*)d_out;
    float* out_att = out + Bv * Cv;

    float *p_xwf, *p_xwb, *p_xzr, *p_xt;
    cudaGetSymbolAddress((void**)&p_xwf, g_xw_f);
    cudaGetSymbolAddress((void**)&p_xwb, g_xw_b);
    cudaGetSymbolAddress((void**)&p_xzr, g_xzr);
    cudaGetSymbolAddress((void**)&p_xt,  g_xt);

    // 1) input projections
    proj_gemm<<<dim3(G3 / 64, (Tv * Bv) / 128), 256>>>(x, att_wi_f, att_bi_f, p_xwf, G3);
    proj_gemm<<<dim3(G3 / 64, (Tv * Bv) / 128), 256>>>(x, att_wi_b, att_bi_b, p_xwb, G3);
    proj_gemm<<<dim3(G2 / 64, (Tv * Bv) / 128), 256>>>(x, w_i2h_zr, b_i2h_zr, p_xzr, G2);
    proj_gemm<<<dim3(Hv / 64, (Tv * Bv) / 128), 256>>>(x, w_i2h_t,  b_i2h_t,  p_xt,  Hv);

    // 2) bidirectional GRU — persistent, split-K
    gru_persist<<<256, 128>>>(att_wh_f, att_wh_b, att_bh_f, att_bh_b);

    // 3) attention gate
    att_kernel<<<Tv, 256>>>(att_fc_w, att_fc_b, out_att);

    // 4) TAGM — persistent, split-K
    tagm_persist<<<256, 128>>>(w_h2h_zr, b_h2h_zr, w_h2h_t, b_h2h_t);

    // 5) final projection
    fc0_kernel<<<Bv, 256>>>(fc0_w, fc0_b, out);
}